// round 9
// baseline (speedup 1.0000x reference)
#include <cuda_runtime.h>
#include <cuda_bf16.h>
#include <stdint.h>

#define N_SP 4096
#define CDIM 64
#define MIDD 8
#define BDIM 4
#define NB 32             // n rows per CTA
#define MB 64             // m per tile
#define NSTEP 32          // each m-group does 32 tiles of 64
#define LOG2E 1.4426950408889634f

// ---- attn smem layout (bytes) ----
#define QS_OFF 0                      // 32 rows x 16B
#define KB_OFF 1024                   // 4 bufs x 64 x 16B
#define VB_OFF 5120                   // 4 bufs x 64c x 144B
#define VSTRB 144
#define SM_TOTAL (5120 + 4 * 64 * VSTRB)   // 41984
// epilogue overlays (loop buffers dead):
#define EP_DSM 0                      // 32 floats
#define EP_RS  512                    // 32 floats
#define EP_OS  4096                   // 64c x 36 floats
#define OSTR 36

typedef unsigned long long ull;

// bf16 scratch (allocation-free rule: __device__ globals)
__device__ __nv_bfloat16 g_qb[BDIM * N_SP * MIDD];   // [b][n][8c], pre-scaled by log2e
__device__ __nv_bfloat16 g_kb[BDIM * N_SP * MIDD];   // [b][m][8c]
__device__ __nv_bfloat16 g_vb[BDIM * CDIM * N_SP];   // [b][c][m]

__device__ __forceinline__ uint32_t smem_u32(const void* p) {
    uint32_t a;
    asm("{ .reg .u64 t; cvta.to.shared.u64 t, %1; cvt.u32.u64 %0, t; }"
        : "=r"(a) : "l"(p));
    return a;
}
__device__ __forceinline__ void ldsm_x2(uint32_t& r0, uint32_t& r1, uint32_t a) {
    asm volatile("ldmatrix.sync.aligned.m8n8.x2.shared.b16 {%0,%1}, [%2];"
                 : "=r"(r0), "=r"(r1) : "r"(a));
}
__device__ __forceinline__ void ldsm_x4(uint32_t& r0, uint32_t& r1,
                                        uint32_t& r2, uint32_t& r3, uint32_t a) {
    asm volatile("ldmatrix.sync.aligned.m8n8.x4.shared.b16 {%0,%1,%2,%3}, [%4];"
                 : "=r"(r0), "=r"(r1), "=r"(r2), "=r"(r3) : "r"(a));
}
__device__ __forceinline__ void mma_16808(float* d, uint32_t a0, uint32_t a1,
                                          uint32_t b0) {
    asm volatile(
        "mma.sync.aligned.m16n8k8.row.col.f32.bf16.bf16.f32 "
        "{%0,%1,%2,%3}, {%4,%5}, {%6}, {%7,%7,%7,%7};"
        : "=f"(d[0]), "=f"(d[1]), "=f"(d[2]), "=f"(d[3])
        : "r"(a0), "r"(a1), "r"(b0), "f"(0.f));
}
__device__ __forceinline__ void mma_16816(float* d, const uint32_t* a,
                                          uint32_t b0, uint32_t b1) {
    asm volatile(
        "mma.sync.aligned.m16n8k16.row.col.f32.bf16.bf16.f32 "
        "{%0,%1,%2,%3}, {%4,%5,%6,%7}, {%8,%9}, {%0,%1,%2,%3};"
        : "+f"(d[0]), "+f"(d[1]), "+f"(d[2]), "+f"(d[3])
        : "r"(a[0]), "r"(a[1]), "r"(a[2]), "r"(a[3]), "r"(b0), "r"(b1));
}
__device__ __forceinline__ uint32_t pack_bf(float even, float odd) {
    uint32_t r;
    asm("cvt.rn.bf16x2.f32 %0, %1, %2;" : "=r"(r) : "f"(odd), "f"(even));
    return r;
}
__device__ __forceinline__ float ex2(float v) {
    float r;
    asm("ex2.approx.f32 %0, %1;" : "=f"(r) : "f"(v));
    return r;
}
__device__ __forceinline__ ull f2fma(ull a, ull b, ull c) {
    ull d;
    asm("fma.rn.f32x2 %0, %1, %2, %3;" : "=l"(d) : "l"(a), "l"(b), "l"(c));
    return d;
}
__device__ __forceinline__ ull pk2(float x, float y) {
    ull r;
    asm("mov.b64 %0, {%1, %2};" : "=l"(r) : "f"(x), "f"(y));
    return r;
}
__device__ __forceinline__ float2 upk2(ull v) {
    float2 r;
    asm("mov.b64 {%0, %1}, %2;" : "=f"(r.x), "=f"(r.y) : "l"(v));
    return r;
}
__device__ __forceinline__ void cpasync16(uint32_t dst, const void* src) {
    asm volatile("cp.async.ca.shared.global [%0], [%1], 16;" :: "r"(dst), "l"(src));
}
#define CP_COMMIT() asm volatile("cp.async.commit_group;" ::: "memory")

// ---------------------------------------------------------------------------
// Kernel 1: 1x1-conv projections, 5-role split for occupancy.
//   role 0: q (8 outs, pre-scaled by log2e) + k (8 outs)
//   role r=1..4: v channels [(r-1)*16, r*16)
// grid = 640 blocks x 128 threads; block -> (p0 = (blk/5)*128, role = blk%5).
// x processed in two 32-channel chunks to bound live registers (~80).
// ---------------------------------------------------------------------------
__global__ __launch_bounds__(128) void qkv_kernel(
    const float* __restrict__ x,
    const float* __restrict__ Wq, const float* __restrict__ bq,
    const float* __restrict__ Wk, const float* __restrict__ bk,
    const float* __restrict__ Wv, const float* __restrict__ bv)
{
    __shared__ __align__(16) float sW[16 * CDIM];
    __shared__ float sbias[16];

    int tid = threadIdx.x;
    int role = blockIdx.x % 5;
    int p = (blockIdx.x / 5) * 128 + tid;
    int b = p >> 12;
    int n = p & (N_SP - 1);

    if (role == 0) {
        for (int i = tid; i < MIDD * CDIM; i += 128) {
            sW[i] = Wq[i] * LOG2E;
            sW[MIDD * CDIM + i] = Wk[i];
        }
        if (tid < MIDD) { sbias[tid] = bq[tid] * LOG2E; sbias[MIDD + tid] = bk[tid]; }
    } else {
        int off = (role - 1) * 16 * CDIM;
        for (int i = tid; i < 16 * CDIM; i += 128) sW[i] = Wv[off + i];
        if (tid < 16) sbias[tid] = bv[(role - 1) * 16 + tid];
    }
    __syncthreads();

    ull acc[16];
#pragma unroll
    for (int o = 0; o < 16; o++) acc[o] = 0ULL;

    const float* xp = x + (size_t)(b * CDIM) * N_SP + n;
#pragma unroll
    for (int chunk = 0; chunk < 2; chunk++) {
        ull xd[16];
#pragma unroll
        for (int j = 0; j < 16; j++) {
            float a = xp[(chunk * 32 + 2 * j) * N_SP];
            float bb = xp[(chunk * 32 + 2 * j + 1) * N_SP];
            xd[j] = pk2(a, bb);
        }
#pragma unroll
        for (int o = 0; o < 16; o++) {
            const ulonglong2* wp =
                reinterpret_cast<const ulonglong2*>(&sW[o * CDIM + chunk * 32]);
            ull a = acc[o];
#pragma unroll
            for (int i = 0; i < 8; i++) {
                ulonglong2 w = wp[i];
                a = f2fma(w.x, xd[2 * i], a);
                a = f2fma(w.y, xd[2 * i + 1], a);
            }
            acc[o] = a;
        }
    }

    float res[16];
#pragma unroll
    for (int o = 0; o < 16; o++) {
        float2 u = upk2(acc[o]);
        res[o] = u.x + u.y + sbias[o];
    }

    if (role == 0) {
        uint4 u;
        __nv_bfloat162 t0 = __floats2bfloat162_rn(res[0], res[1]);
        __nv_bfloat162 t1 = __floats2bfloat162_rn(res[2], res[3]);
        __nv_bfloat162 t2 = __floats2bfloat162_rn(res[4], res[5]);
        __nv_bfloat162 t3 = __floats2bfloat162_rn(res[6], res[7]);
        u.x = *(uint32_t*)&t0; u.y = *(uint32_t*)&t1;
        u.z = *(uint32_t*)&t2; u.w = *(uint32_t*)&t3;
        *(uint4*)(g_qb + (size_t)(b * N_SP + n) * MIDD) = u;
        t0 = __floats2bfloat162_rn(res[8], res[9]);
        t1 = __floats2bfloat162_rn(res[10], res[11]);
        t2 = __floats2bfloat162_rn(res[12], res[13]);
        t3 = __floats2bfloat162_rn(res[14], res[15]);
        u.x = *(uint32_t*)&t0; u.y = *(uint32_t*)&t1;
        u.z = *(uint32_t*)&t2; u.w = *(uint32_t*)&t3;
        *(uint4*)(g_kb + (size_t)(b * N_SP + n) * MIDD) = u;
    } else {
        int c0 = (role - 1) * 16;
#pragma unroll
        for (int j = 0; j < 16; j++)
            g_vb[(size_t)(b * CDIM + c0 + j) * N_SP + n] = __float2bfloat16(res[j]);
    }
}

// ---------------------------------------------------------------------------
// Kernel 2: HMMA flash attention, NB=32 / grid=512 / 3 CTAs per SM.
// CTA = 128 thr (4 warps); warp w: m-group mg=w&1, rows (w>>1)*16 .. +16.
// Per warp: one m16 A-frag, 32 O-accums; cp.async double-buffered K/V.
// ---------------------------------------------------------------------------
__global__ __launch_bounds__(128, 3) void attn_kernel(
    const float* __restrict__ x,
    const float* __restrict__ gamma,
    float* __restrict__ out)
{
    __shared__ __align__(16) char smem[SM_TOTAL];
    uint32_t sb = smem_u32(smem);

    int tid = threadIdx.x;
    int w = tid >> 5;
    int t = tid & 31;
    int mg = w & 1;
    int wrow = (w >> 1) * 16;
    int b = blockIdx.x >> 7;
    int n0 = (blockIdx.x & 127) * NB;

    const __nv_bfloat16* vb0 = g_vb + (size_t)b * CDIM * N_SP;
    const __nv_bfloat16* kb0 = g_kb + (size_t)b * N_SP * MIDD;

    // ---- stage Q tile [32 rows][16B] ----
    if (tid < NB) {
        *(uint4*)(smem + QS_OFF + tid * 16) =
            *(const uint4*)(g_qb + (size_t)(b * N_SP + n0 + tid) * MIDD);
    }

    // ---- prologue: tiles 0,1 -> parity-0 buffers ----
    {
#pragma unroll
        for (int i = 0; i < 8; i++) {
            int ch = tid + 128 * i;
            int tile = ch >> 9;
            int c2 = ch & 511;
            int c = c2 >> 3, q8 = c2 & 7;
            cpasync16(sb + VB_OFF + (tile * 2) * (64 * VSTRB) + c * VSTRB + q8 * 16,
                      vb0 + c * N_SP + tile * MB + q8 * 8);
        }
        {
            int tile = tid >> 6, row = tid & 63;
            cpasync16(sb + KB_OFF + (tile * 2) * 1024 + row * 16,
                      kb0 + (tile * MB + row) * MIDD);
        }
        CP_COMMIT();
    }
    __syncthreads();

    // Q A-frag: rows wrow..wrow+15
    uint32_t qa0, qa1;
    ldsm_x2(qa0, qa1, sb + QS_OFF + (wrow + (t & 15)) * 16);

    float o0[8][4];
#pragma unroll
    for (int g2 = 0; g2 < 8; g2++)
#pragma unroll
        for (int j = 0; j < 4; j++) o0[g2][j] = 0.f;
    float dA = 0.f, dB = 0.f;

    int crow_base = ((t & 16) >> 1) + (t & 7);
    int col_base = ((t >> 3) & 1) * 8;

    for (int step = 0; step < NSTEP; step++) {
        // issue next pair of tiles
        if (step + 1 < NSTEP) {
            int par = (step + 1) & 1;
            int m0n = 2 * (step + 1) * MB;
#pragma unroll
            for (int i = 0; i < 8; i++) {
                int ch = tid + 128 * i;
                int tile = ch >> 9;
                int c2 = ch & 511;
                int c = c2 >> 3, q8 = c2 & 7;
                cpasync16(sb + VB_OFF + (tile * 2 + par) * (64 * VSTRB) + c * VSTRB + q8 * 16,
                          vb0 + c * N_SP + m0n + tile * MB + q8 * 8);
            }
            {
                int tile = tid >> 6, row = tid & 63;
                cpasync16(sb + KB_OFF + (tile * 2 + par) * 1024 + row * 16,
                          kb0 + (m0n + tile * MB + row) * MIDD);
            }
            CP_COMMIT();
            asm volatile("cp.async.wait_group 1;" ::: "memory");
        } else {
            asm volatile("cp.async.wait_group 0;" ::: "memory");
        }
        __syncthreads();

        int par = step & 1;
        uint32_t kbase = sb + KB_OFF + (mg * 2 + par) * 1024;
        uint32_t vbase = sb + VB_OFF + (mg * 2 + par) * (64 * VSTRB);

#pragma unroll
        for (int kh = 0; kh < 2; kh++) {
            uint32_t kb4[4];
            ldsm_x4(kb4[0], kb4[1], kb4[2], kb4[3], kbase + (kh * 32 + t) * 16);
#pragma unroll
            for (int ks2 = 0; ks2 < 2; ks2++) {
                int ks = kh * 2 + ks2;
                uint32_t p[4];
#pragma unroll
                for (int hf = 0; hf < 2; hf++) {
                    float d[4];
                    mma_16808(d, qa0, qa1, kb4[ks2 * 2 + hf]);
                    float e0 = ex2(d[0]), e1 = ex2(d[1]);
                    float e2 = ex2(d[2]), e3 = ex2(d[3]);
                    dA += e0 + e1; dB += e2 + e3;
                    p[hf * 2]     = pack_bf(e0, e1);
                    p[hf * 2 + 1] = pack_bf(e2, e3);
                }
#pragma unroll
                for (int gp = 0; gp < 4; gp++) {
                    int crow = gp * 16 + crow_base;
                    int col = ks * 16 + col_base;
                    uint32_t r0, r1, r2, r3;
                    ldsm_x4(r0, r1, r2, r3, vbase + crow * VSTRB + col * 2);
                    mma_16816(o0[gp * 2],     p, r0, r1);
                    mma_16816(o0[gp * 2 + 1], p, r2, r3);
                }
            }
        }
        __syncthreads();
    }

    // ---- denominators: lane-quad reduce, then combine m-groups in smem ----
    dA += __shfl_xor_sync(~0u, dA, 1); dA += __shfl_xor_sync(~0u, dA, 2);
    dB += __shfl_xor_sync(~0u, dB, 1); dB += __shfl_xor_sync(~0u, dB, 2);

    float* dsm = (float*)(smem + EP_DSM);
    float* rs  = (float*)(smem + EP_RS);
    float* Os  = (float*)(smem + EP_OS);
    int nA = wrow + (t >> 2);

    if (mg == 0) {
        if ((t & 3) == 0) { dsm[nA] = dA; dsm[nA + 8] = dB; }
#pragma unroll
        for (int g2 = 0; g2 < 8; g2++) {
            int c0 = g2 * 8 + 2 * (t & 3);
            Os[c0 * OSTR + nA]           = o0[g2][0];
            Os[(c0 + 1) * OSTR + nA]     = o0[g2][1];
            Os[c0 * OSTR + nA + 8]       = o0[g2][2];
            Os[(c0 + 1) * OSTR + nA + 8] = o0[g2][3];
        }
    }
    __syncthreads();
    if (mg == 1) {
        if ((t & 3) == 0) { dsm[nA] += dA; dsm[nA + 8] += dB; }
#pragma unroll
        for (int g2 = 0; g2 < 8; g2++) {
            int c0 = g2 * 8 + 2 * (t & 3);
            Os[c0 * OSTR + nA]           += o0[g2][0];
            Os[(c0 + 1) * OSTR + nA]     += o0[g2][1];
            Os[c0 * OSTR + nA + 8]       += o0[g2][2];
            Os[(c0 + 1) * OSTR + nA + 8] += o0[g2][3];
        }
    }
    __syncthreads();
    if (tid < NB) rs[tid] = gamma[0] / dsm[tid];
    __syncthreads();

    // ---- coalesced write: out[c][n] = Os*rs + x ----
#pragma unroll
    for (int rr = 0; rr < 4; rr++) {
        int f = tid + 128 * rr;          // float4 id: 64 c-rows x 8 per row
        int c = f >> 3, j4 = f & 7;
        float4 o = *(float4*)&Os[c * OSTR + j4 * 4];
        float4 rv = *(float4*)&rs[j4 * 4];
        size_t base = (size_t)(b * CDIM + c) * N_SP + n0 + j4 * 4;
        float4 xv = *(const float4*)&x[base];
        o.x = fmaf(o.x, rv.x, xv.x);
        o.y = fmaf(o.y, rv.y, xv.y);
        o.z = fmaf(o.z, rv.z, xv.z);
        o.w = fmaf(o.w, rv.w, xv.w);
        *(float4*)&out[base] = o;
    }
}

// ---------------------------------------------------------------------------
extern "C" void kernel_launch(void* const* d_in, const int* in_sizes, int n_in,
                              void* d_out, int out_size)
{
    const float* x     = (const float*)d_in[0];
    const float* Wq    = (const float*)d_in[1];
    const float* bq    = (const float*)d_in[2];
    const float* Wk    = (const float*)d_in[3];
    const float* bk    = (const float*)d_in[4];
    const float* Wv    = (const float*)d_in[5];
    const float* bv    = (const float*)d_in[6];
    const float* gamma = (const float*)d_in[7];
    float* out = (float*)d_out;

    qkv_kernel<<<640, 128>>>(x, Wq, bq, Wk, bk, Wv, bv);
    attn_kernel<<<BDIM * (N_SP / NB), 128>>>(x, gamma, out);
}

// round 11
// speedup vs baseline: 1.1704x; 1.1704x over previous
#include <cuda_runtime.h>
#include <cuda_bf16.h>
#include <stdint.h>

#define N_SP 4096
#define CDIM 64
#define MIDD 8
#define BDIM 4
#define NB 64             // n rows per CTA
#define MB 64             // m per tile
#define NSTEP 32          // each m-group does 32 tiles of 64
#define LOG2E 1.4426950408889634f

// ---- attn smem layout (bytes) ----
#define QS_OFF 0                      // 64 rows x 16B
#define KB_OFF 1024                   // 4 bufs x 64 x 16B
#define VB_OFF 5120                   // 4 bufs x 64c x 144B
#define VSTRB 144
#define SM_TOTAL (5120 + 4 * 64 * VSTRB)   // 41984
// epilogue overlays (loop buffers dead):
#define EP_DSM 0                      // 64 floats
#define EP_RS  512                    // 64 floats
#define EP_OS  4096                   // 64c x 68 floats
#define OSTR 68

typedef unsigned long long ull;

// bf16 scratch (allocation-free rule: __device__ globals)
__device__ __nv_bfloat16 g_qb[BDIM * N_SP * MIDD];   // [b][n][8c], pre-scaled by log2e
__device__ __nv_bfloat16 g_kb[BDIM * N_SP * MIDD];   // [b][m][8c]
__device__ __nv_bfloat16 g_vb[BDIM * CDIM * N_SP];   // [b][c][m]

__device__ __forceinline__ uint32_t smem_u32(const void* p) {
    uint32_t a;
    asm("{ .reg .u64 t; cvta.to.shared.u64 t, %1; cvt.u32.u64 %0, t; }"
        : "=r"(a) : "l"(p));
    return a;
}
__device__ __forceinline__ void ldsm_x4(uint32_t& r0, uint32_t& r1,
                                        uint32_t& r2, uint32_t& r3, uint32_t a) {
    asm volatile("ldmatrix.sync.aligned.m8n8.x4.shared.b16 {%0,%1,%2,%3}, [%4];"
                 : "=r"(r0), "=r"(r1), "=r"(r2), "=r"(r3) : "r"(a));
}
__device__ __forceinline__ void mma_16808(float* d, uint32_t a0, uint32_t a1,
                                          uint32_t b0) {
    asm volatile(
        "mma.sync.aligned.m16n8k8.row.col.f32.bf16.bf16.f32 "
        "{%0,%1,%2,%3}, {%4,%5}, {%6}, {%7,%7,%7,%7};"
        : "=f"(d[0]), "=f"(d[1]), "=f"(d[2]), "=f"(d[3])
        : "r"(a0), "r"(a1), "r"(b0), "f"(0.f));
}
__device__ __forceinline__ void mma_16816(float* d, const uint32_t* a,
                                          uint32_t b0, uint32_t b1) {
    asm volatile(
        "mma.sync.aligned.m16n8k16.row.col.f32.bf16.bf16.f32 "
        "{%0,%1,%2,%3}, {%4,%5,%6,%7}, {%8,%9}, {%0,%1,%2,%3};"
        : "+f"(d[0]), "+f"(d[1]), "+f"(d[2]), "+f"(d[3])
        : "r"(a[0]), "r"(a[1]), "r"(a[2]), "r"(a[3]), "r"(b0), "r"(b1));
}
__device__ __forceinline__ uint32_t pack_bf(float even, float odd) {
    uint32_t r;
    asm("cvt.rn.bf16x2.f32 %0, %1, %2;" : "=r"(r) : "f"(odd), "f"(even));
    return r;
}
__device__ __forceinline__ float ex2(float v) {
    float r;
    asm("ex2.approx.f32 %0, %1;" : "=f"(r) : "f"(v));
    return r;
}
__device__ __forceinline__ ull f2fma(ull a, ull b, ull c) {
    ull d;
    asm("fma.rn.f32x2 %0, %1, %2, %3;" : "=l"(d) : "l"(a), "l"(b), "l"(c));
    return d;
}
__device__ __forceinline__ ull pk2(float x, float y) {
    ull r;
    asm("mov.b64 %0, {%1, %2};" : "=l"(r) : "f"(x), "f"(y));
    return r;
}
__device__ __forceinline__ float2 upk2(ull v) {
    float2 r;
    asm("mov.b64 {%0, %1}, %2;" : "=f"(r.x), "=f"(r.y) : "l"(v));
    return r;
}
__device__ __forceinline__ void cpasync16(uint32_t dst, const void* src) {
    asm volatile("cp.async.ca.shared.global [%0], [%1], 16;" :: "r"(dst), "l"(src));
}
#define CP_COMMIT() asm volatile("cp.async.commit_group;" ::: "memory")

// ---------------------------------------------------------------------------
// Kernel 1: 1x1-conv projections, 5-role split (R9, measured ~7.5us).
//   role 0: q (8 outs, pre-scaled by log2e) + k (8 outs)
//   role r=1..4: v channels [(r-1)*16, r*16)
// ---------------------------------------------------------------------------
__global__ __launch_bounds__(128) void qkv_kernel(
    const float* __restrict__ x,
    const float* __restrict__ Wq, const float* __restrict__ bq,
    const float* __restrict__ Wk, const float* __restrict__ bk,
    const float* __restrict__ Wv, const float* __restrict__ bv)
{
    __shared__ __align__(16) float sW[16 * CDIM];
    __shared__ float sbias[16];

    int tid = threadIdx.x;
    int role = blockIdx.x % 5;
    int p = (blockIdx.x / 5) * 128 + tid;
    int b = p >> 12;
    int n = p & (N_SP - 1);

    if (role == 0) {
        for (int i = tid; i < MIDD * CDIM; i += 128) {
            sW[i] = Wq[i] * LOG2E;
            sW[MIDD * CDIM + i] = Wk[i];
        }
        if (tid < MIDD) { sbias[tid] = bq[tid] * LOG2E; sbias[MIDD + tid] = bk[tid]; }
    } else {
        int off = (role - 1) * 16 * CDIM;
        for (int i = tid; i < 16 * CDIM; i += 128) sW[i] = Wv[off + i];
        if (tid < 16) sbias[tid] = bv[(role - 1) * 16 + tid];
    }
    __syncthreads();

    ull acc[16];
#pragma unroll
    for (int o = 0; o < 16; o++) acc[o] = 0ULL;

    const float* xp = x + (size_t)(b * CDIM) * N_SP + n;
#pragma unroll
    for (int chunk = 0; chunk < 2; chunk++) {
        ull xd[16];
#pragma unroll
        for (int j = 0; j < 16; j++) {
            float a = xp[(chunk * 32 + 2 * j) * N_SP];
            float bb = xp[(chunk * 32 + 2 * j + 1) * N_SP];
            xd[j] = pk2(a, bb);
        }
#pragma unroll
        for (int o = 0; o < 16; o++) {
            const ulonglong2* wp =
                reinterpret_cast<const ulonglong2*>(&sW[o * CDIM + chunk * 32]);
            ull a = acc[o];
#pragma unroll
            for (int i = 0; i < 8; i++) {
                ulonglong2 w = wp[i];
                a = f2fma(w.x, xd[2 * i], a);
                a = f2fma(w.y, xd[2 * i + 1], a);
            }
            acc[o] = a;
        }
    }

    float res[16];
#pragma unroll
    for (int o = 0; o < 16; o++) {
        float2 u = upk2(acc[o]);
        res[o] = u.x + u.y + sbias[o];
    }

    if (role == 0) {
        uint4 u;
        __nv_bfloat162 t0 = __floats2bfloat162_rn(res[0], res[1]);
        __nv_bfloat162 t1 = __floats2bfloat162_rn(res[2], res[3]);
        __nv_bfloat162 t2 = __floats2bfloat162_rn(res[4], res[5]);
        __nv_bfloat162 t3 = __floats2bfloat162_rn(res[6], res[7]);
        u.x = *(uint32_t*)&t0; u.y = *(uint32_t*)&t1;
        u.z = *(uint32_t*)&t2; u.w = *(uint32_t*)&t3;
        *(uint4*)(g_qb + (size_t)(b * N_SP + n) * MIDD) = u;
        t0 = __floats2bfloat162_rn(res[8], res[9]);
        t1 = __floats2bfloat162_rn(res[10], res[11]);
        t2 = __floats2bfloat162_rn(res[12], res[13]);
        t3 = __floats2bfloat162_rn(res[14], res[15]);
        u.x = *(uint32_t*)&t0; u.y = *(uint32_t*)&t1;
        u.z = *(uint32_t*)&t2; u.w = *(uint32_t*)&t3;
        *(uint4*)(g_kb + (size_t)(b * N_SP + n) * MIDD) = u;
    } else {
        int c0 = (role - 1) * 16;
#pragma unroll
        for (int j = 0; j < 16; j++)
            g_vb[(size_t)(b * CDIM + c0 + j) * N_SP + n] = __float2bfloat16(res[j]);
    }
}

// ---------------------------------------------------------------------------
// Kernel 2: HMMA flash attention (R8 shape: NB=64, MB=64, grid 256, 4 warps,
// mg=w&1, rows (w>>1)*32), with ks-level SOFTWARE PIPELINE:
//   QK+exp+pack of K-step ks+1 issues BEFORE the PV MMAs of K-step ks,
//   and V fragments are prefetched one ldsm ahead.
// ---------------------------------------------------------------------------
__global__ __launch_bounds__(128, 2) void attn_kernel(
    const float* __restrict__ x,
    const float* __restrict__ gamma,
    float* __restrict__ out)
{
    __shared__ __align__(16) char smem[SM_TOTAL];
    uint32_t sb = smem_u32(smem);

    int tid = threadIdx.x;
    int w = tid >> 5;
    int t = tid & 31;
    int mg = w & 1;
    int wrow = (w >> 1) * 32;
    int b = blockIdx.x >> 6;
    int n0 = (blockIdx.x & 63) * NB;

    const __nv_bfloat16* vb0 = g_vb + (size_t)b * CDIM * N_SP;
    const __nv_bfloat16* kb0 = g_kb + (size_t)b * N_SP * MIDD;

    // ---- stage Q tile [64 rows][16B] ----
    if (tid < NB) {
        *(uint4*)(smem + QS_OFF + tid * 16) =
            *(const uint4*)(g_qb + (size_t)(b * N_SP + n0 + tid) * MIDD);
    }

    // ---- prologue: tiles 0,1 -> parity-0 buffers ----
    {
#pragma unroll
        for (int i = 0; i < 8; i++) {
            int ch = tid + 128 * i;
            int tile = ch >> 9;
            int c2 = ch & 511;
            int c = c2 >> 3, q8 = c2 & 7;
            cpasync16(sb + VB_OFF + (tile * 2) * (64 * VSTRB) + c * VSTRB + q8 * 16,
                      vb0 + c * N_SP + tile * MB + q8 * 8);
        }
        {
            int tile = tid >> 6, row = tid & 63;
            cpasync16(sb + KB_OFF + (tile * 2) * 1024 + row * 16,
                      kb0 + (tile * MB + row) * MIDD);
        }
        CP_COMMIT();
    }
    __syncthreads();

    // Q A-frags: rows wrow..wrow+31
    uint32_t qa[4];
    ldsm_x4(qa[0], qa[1], qa[2], qa[3], sb + QS_OFF + (wrow + t) * 16);

    float o0[8][4], o1[8][4];
#pragma unroll
    for (int g2 = 0; g2 < 8; g2++)
#pragma unroll
        for (int j = 0; j < 4; j++) { o0[g2][j] = 0.f; o1[g2][j] = 0.f; }
    float d0A = 0.f, d0B = 0.f, d1A = 0.f, d1B = 0.f;

    int crow_base = ((t & 16) >> 1) + (t & 7);
    int col_base = ((t >> 3) & 1) * 8;

    for (int step = 0; step < NSTEP; step++) {
        // issue next pair of tiles
        if (step + 1 < NSTEP) {
            int par = (step + 1) & 1;
            int m0n = 2 * (step + 1) * MB;
#pragma unroll
            for (int i = 0; i < 8; i++) {
                int ch = tid + 128 * i;
                int tile = ch >> 9;
                int c2 = ch & 511;
                int c = c2 >> 3, q8 = c2 & 7;
                cpasync16(sb + VB_OFF + (tile * 2 + par) * (64 * VSTRB) + c * VSTRB + q8 * 16,
                          vb0 + c * N_SP + m0n + tile * MB + q8 * 8);
            }
            {
                int tile = tid >> 6, row = tid & 63;
                cpasync16(sb + KB_OFF + (tile * 2 + par) * 1024 + row * 16,
                          kb0 + (m0n + tile * MB + row) * MIDD);
            }
            CP_COMMIT();
            asm volatile("cp.async.wait_group 1;" ::: "memory");
        } else {
            asm volatile("cp.async.wait_group 0;" ::: "memory");
        }
        __syncthreads();

        int par = step & 1;
        uint32_t kbase = sb + KB_OFF + (mg * 2 + par) * 1024;
        uint32_t vbase = sb + VB_OFF + (mg * 2 + par) * (64 * VSTRB);

        // ---- all K B-frags for the step (independent of everything) ----
        uint32_t kb[8];
        ldsm_x4(kb[0], kb[1], kb[2], kb[3], kbase + t * 16);
        ldsm_x4(kb[4], kb[5], kb[6], kb[7], kbase + (32 + t) * 16);

        // QK stage lambda: produce packed P for one K-step
        auto qk_stage = [&](int ks, uint32_t* P0, uint32_t* P1) {
#pragma unroll
            for (int hf = 0; hf < 2; hf++) {
                float d0[4], d1[4];
                mma_16808(d0, qa[0], qa[1], kb[ks * 2 + hf]);
                mma_16808(d1, qa[2], qa[3], kb[ks * 2 + hf]);
                float e00 = ex2(d0[0]), e01 = ex2(d0[1]);
                float e02 = ex2(d0[2]), e03 = ex2(d0[3]);
                float e10 = ex2(d1[0]), e11 = ex2(d1[1]);
                float e12 = ex2(d1[2]), e13 = ex2(d1[3]);
                d0A += e00 + e01; d0B += e02 + e03;
                d1A += e10 + e11; d1B += e12 + e13;
                P0[hf * 2]     = pack_bf(e00, e01);
                P0[hf * 2 + 1] = pack_bf(e02, e03);
                P1[hf * 2]     = pack_bf(e10, e11);
                P1[hf * 2 + 1] = pack_bf(e12, e13);
            }
        };
        // V fragment loader by flat index (ks*4 + gp)
        auto ldV = [&](uint32_t* v, int flat) {
            int ks = flat >> 2, gp = flat & 3;
            ldsm_x4(v[0], v[1], v[2], v[3],
                    vbase + (gp * 16 + crow_base) * VSTRB + (ks * 16 + col_base) * 2);
        };

        uint32_t pa0[4], pa1[4], pb0[4], pb1[4];
        uint32_t vc[4], vn[4];

        qk_stage(0, pa0, pa1);     // P for ks=0
        ldV(vc, 0);                // V frag (ks=0, gp=0)

#pragma unroll
        for (int ks = 0; ks < 4; ks++) {
            // next K-step's QK+exp+pack BEFORE this K-step's PV (pipe overlap)
            if (ks < 3) qk_stage(ks + 1, pb0, pb1);
#pragma unroll
            for (int gp = 0; gp < 4; gp++) {
                int nxt = ks * 4 + gp + 1;
                if (nxt < 16) ldV(vn, nxt);     // prefetch next V frag
                mma_16816(o0[gp * 2],     pa0, vc[0], vc[1]);
                mma_16816(o0[gp * 2 + 1], pa0, vc[2], vc[3]);
                mma_16816(o1[gp * 2],     pa1, vc[0], vc[1]);
                mma_16816(o1[gp * 2 + 1], pa1, vc[2], vc[3]);
#pragma unroll
                for (int j = 0; j < 4; j++) vc[j] = vn[j];
            }
            if (ks < 3) {
#pragma unroll
                for (int j = 0; j < 4; j++) { pa0[j] = pb0[j]; pa1[j] = pb1[j]; }
            }
        }
        __syncthreads();
    }

    // ---- denominators: lane-quad reduce, then combine m-groups in smem ----
    d0A += __shfl_xor_sync(~0u, d0A, 1); d0A += __shfl_xor_sync(~0u, d0A, 2);
    d0B += __shfl_xor_sync(~0u, d0B, 1); d0B += __shfl_xor_sync(~0u, d0B, 2);
    d1A += __shfl_xor_sync(~0u, d1A, 1); d1A += __shfl_xor_sync(~0u, d1A, 2);
    d1B += __shfl_xor_sync(~0u, d1B, 1); d1B += __shfl_xor_sync(~0u, d1B, 2);

    float* dsm = (float*)(smem + EP_DSM);
    float* rs  = (float*)(smem + EP_RS);
    float* Os  = (float*)(smem + EP_OS);
    int r0w = wrow + (t >> 2);

    if (mg == 0) {
        if ((t & 3) == 0) {
            dsm[r0w] = d0A; dsm[r0w + 8] = d0B;
            dsm[r0w + 16] = d1A; dsm[r0w + 24] = d1B;
        }
#pragma unroll
        for (int g2 = 0; g2 < 8; g2++) {
            int c0 = g2 * 8 + 2 * (t & 3);
            int nA = wrow + (t >> 2);
            Os[c0 * OSTR + nA]            = o0[g2][0];
            Os[(c0 + 1) * OSTR + nA]      = o0[g2][1];
            Os[c0 * OSTR + nA + 8]        = o0[g2][2];
            Os[(c0 + 1) * OSTR + nA + 8]  = o0[g2][3];
            Os[c0 * OSTR + nA + 16]       = o1[g2][0];
            Os[(c0 + 1) * OSTR + nA + 16] = o1[g2][1];
            Os[c0 * OSTR + nA + 24]       = o1[g2][2];
            Os[(c0 + 1) * OSTR + nA + 24] = o1[g2][3];
        }
    }
    __syncthreads();
    if (mg == 1) {
        if ((t & 3) == 0) {
            dsm[r0w] += d0A; dsm[r0w + 8] += d0B;
            dsm[r0w + 16] += d1A; dsm[r0w + 24] += d1B;
        }
#pragma unroll
        for (int g2 = 0; g2 < 8; g2++) {
            int c0 = g2 * 8 + 2 * (t & 3);
            int nA = wrow + (t >> 2);
            Os[c0 * OSTR + nA]            += o0[g2][0];
            Os[(c0 + 1) * OSTR + nA]      += o0[g2][1];
            Os[c0 * OSTR + nA + 8]        += o0[g2][2];
            Os[(c0 + 1) * OSTR + nA + 8]  += o0[g2][3];
            Os[c0 * OSTR + nA + 16]       += o1[g2][0];
            Os[(c0 + 1) * OSTR + nA + 16] += o1[g2][1];
            Os[c0 * OSTR + nA + 24]       += o1[g2][2];
            Os[(c0 + 1) * OSTR + nA + 24] += o1[g2][3];
        }
    }
    __syncthreads();
    if (tid < NB) rs[tid] = gamma[0] / dsm[tid];
    __syncthreads();

    // ---- coalesced write: out[c][n] = Os*rs + x ----
#pragma unroll
    for (int rr = 0; rr < 8; rr++) {
        int f = tid + 128 * rr;          // float4 id: 64 c-rows x 16 per row
        int c = f >> 4, j4 = f & 15;
        float4 o = *(float4*)&Os[c * OSTR + j4 * 4];
        float4 rv = *(float4*)&rs[j4 * 4];
        size_t base = (size_t)(b * CDIM + c) * N_SP + n0 + j4 * 4;
        float4 xv = *(const float4*)&x[base];
        o.x = fmaf(o.x, rv.x, xv.x);
        o.y = fmaf(o.y, rv.y, xv.y);
        o.z = fmaf(o.z, rv.z, xv.z);
        o.w = fmaf(o.w, rv.w, xv.w);
        *(float4*)&out[base] = o;
    }
}

// ---------------------------------------------------------------------------
extern "C" void kernel_launch(void* const* d_in, const int* in_sizes, int n_in,
                              void* d_out, int out_size)
{
    const float* x     = (const float*)d_in[0];
    const float* Wq    = (const float*)d_in[1];
    const float* bq    = (const float*)d_in[2];
    const float* Wk    = (const float*)d_in[3];
    const float* bk    = (const float*)d_in[4];
    const float* Wv    = (const float*)d_in[5];
    const float* bv    = (const float*)d_in[6];
    const float* gamma = (const float*)d_in[7];
    float* out = (float*)d_out;

    qkv_kernel<<<640, 128>>>(x, Wq, bq, Wk, bk, Wv, bv);
    attn_kernel<<<BDIM * (N_SP / NB), 128>>>(x, gamma, out);
}

// round 12
// speedup vs baseline: 1.2075x; 1.0317x over previous
#include <cuda_runtime.h>
#include <cuda_bf16.h>
#include <stdint.h>

#define N_SP 4096
#define CDIM 64
#define MIDD 8
#define BDIM 4
#define NB 64             // n rows per CTA
#define MB 64             // m per tile
#define NSTEP 32          // each m-group does 32 tiles of 64
#define LOG2E 1.4426950408889634f

// ---- attn smem layout (bytes) ----
#define QS_OFF 0                      // 64 rows x 16B
#define KB_OFF 1024                   // 4 bufs x 64 x 16B
#define VB_OFF 5120                   // 4 bufs x 64c x 144B
#define VSTRB 144
#define SM_TOTAL (5120 + 4 * 64 * VSTRB)   // 41984
// epilogue overlays (loop buffers dead):
#define EP_DSM 0                      // 64 floats
#define EP_RS  512                    // 64 floats
#define EP_OS  4096                   // 64c x 68 floats
#define OSTR 68

#define ONESB 0x3F803F80u             // bf16x2 (1.0, 1.0)

typedef unsigned long long ull;

// bf16 scratch (allocation-free rule: __device__ globals)
__device__ __nv_bfloat16 g_qb[BDIM * N_SP * MIDD];   // [b][n][8c], pre-scaled by log2e
__device__ __nv_bfloat16 g_kb[BDIM * N_SP * MIDD];   // [b][m][8c]
__device__ __nv_bfloat16 g_vb[BDIM * CDIM * N_SP];   // [b][c][m]

__device__ __forceinline__ uint32_t smem_u32(const void* p) {
    uint32_t a;
    asm("{ .reg .u64 t; cvta.to.shared.u64 t, %1; cvt.u32.u64 %0, t; }"
        : "=r"(a) : "l"(p));
    return a;
}
__device__ __forceinline__ void ldsm_x4(uint32_t& r0, uint32_t& r1,
                                        uint32_t& r2, uint32_t& r3, uint32_t a) {
    asm volatile("ldmatrix.sync.aligned.m8n8.x4.shared.b16 {%0,%1,%2,%3}, [%4];"
                 : "=r"(r0), "=r"(r1), "=r"(r2), "=r"(r3) : "r"(a));
}
__device__ __forceinline__ void mma_16808(float* d, uint32_t a0, uint32_t a1,
                                          uint32_t b0) {
    asm volatile(
        "mma.sync.aligned.m16n8k8.row.col.f32.bf16.bf16.f32 "
        "{%0,%1,%2,%3}, {%4,%5}, {%6}, {%7,%7,%7,%7};"
        : "=f"(d[0]), "=f"(d[1]), "=f"(d[2]), "=f"(d[3])
        : "r"(a0), "r"(a1), "r"(b0), "f"(0.f));
}
__device__ __forceinline__ void mma_16816(float* d, const uint32_t* a,
                                          uint32_t b0, uint32_t b1) {
    asm volatile(
        "mma.sync.aligned.m16n8k16.row.col.f32.bf16.bf16.f32 "
        "{%0,%1,%2,%3}, {%4,%5,%6,%7}, {%8,%9}, {%0,%1,%2,%3};"
        : "+f"(d[0]), "+f"(d[1]), "+f"(d[2]), "+f"(d[3])
        : "r"(a[0]), "r"(a[1]), "r"(a[2]), "r"(a[3]), "r"(b0), "r"(b1));
}
__device__ __forceinline__ uint32_t pack_bf(float even, float odd) {
    uint32_t r;   // lo = even (first col), hi = odd
    asm("cvt.rn.bf16x2.f32 %0, %1, %2;" : "=r"(r) : "f"(odd), "f"(even));
    return r;
}
// exp2 of a packed bf16x2 pair (MUFU, one slot for two values)
__device__ __forceinline__ uint32_t ex2b(uint32_t v) {
    uint32_t r;
    asm("ex2.approx.ftz.bf16x2 %0, %1;" : "=r"(r) : "r"(v));
    return r;
}
__device__ __forceinline__ ull f2fma(ull a, ull b, ull c) {
    ull d;
    asm("fma.rn.f32x2 %0, %1, %2, %3;" : "=l"(d) : "l"(a), "l"(b), "l"(c));
    return d;
}
__device__ __forceinline__ ull pk2(float x, float y) {
    ull r;
    asm("mov.b64 %0, {%1, %2};" : "=l"(r) : "f"(x), "f"(y));
    return r;
}
__device__ __forceinline__ float2 upk2(ull v) {
    float2 r;
    asm("mov.b64 {%0, %1}, %2;" : "=f"(r.x), "=f"(r.y) : "l"(v));
    return r;
}
__device__ __forceinline__ void cpasync16(uint32_t dst, const void* src) {
    asm volatile("cp.async.ca.shared.global [%0], [%1], 16;" :: "r"(dst), "l"(src));
}
#define CP_COMMIT() asm volatile("cp.async.commit_group;" ::: "memory")

// ---------------------------------------------------------------------------
// Kernel 1: 1x1-conv projections, 5-role split (R9, measured ~7.5us).
// ---------------------------------------------------------------------------
__global__ __launch_bounds__(128) void qkv_kernel(
    const float* __restrict__ x,
    const float* __restrict__ Wq, const float* __restrict__ bq,
    const float* __restrict__ Wk, const float* __restrict__ bk,
    const float* __restrict__ Wv, const float* __restrict__ bv)
{
    __shared__ __align__(16) float sW[16 * CDIM];
    __shared__ float sbias[16];

    int tid = threadIdx.x;
    int role = blockIdx.x % 5;
    int p = (blockIdx.x / 5) * 128 + tid;
    int b = p >> 12;
    int n = p & (N_SP - 1);

    if (role == 0) {
        for (int i = tid; i < MIDD * CDIM; i += 128) {
            sW[i] = Wq[i] * LOG2E;
            sW[MIDD * CDIM + i] = Wk[i];
        }
        if (tid < MIDD) { sbias[tid] = bq[tid] * LOG2E; sbias[MIDD + tid] = bk[tid]; }
    } else {
        int off = (role - 1) * 16 * CDIM;
        for (int i = tid; i < 16 * CDIM; i += 128) sW[i] = Wv[off + i];
        if (tid < 16) sbias[tid] = bv[(role - 1) * 16 + tid];
    }
    __syncthreads();

    ull acc[16];
#pragma unroll
    for (int o = 0; o < 16; o++) acc[o] = 0ULL;

    const float* xp = x + (size_t)(b * CDIM) * N_SP + n;
#pragma unroll
    for (int chunk = 0; chunk < 2; chunk++) {
        ull xd[16];
#pragma unroll
        for (int j = 0; j < 16; j++) {
            float a = xp[(chunk * 32 + 2 * j) * N_SP];
            float bb = xp[(chunk * 32 + 2 * j + 1) * N_SP];
            xd[j] = pk2(a, bb);
        }
#pragma unroll
        for (int o = 0; o < 16; o++) {
            const ulonglong2* wp =
                reinterpret_cast<const ulonglong2*>(&sW[o * CDIM + chunk * 32]);
            ull a = acc[o];
#pragma unroll
            for (int i = 0; i < 8; i++) {
                ulonglong2 w = wp[i];
                a = f2fma(w.x, xd[2 * i], a);
                a = f2fma(w.y, xd[2 * i + 1], a);
            }
            acc[o] = a;
        }
    }

    float res[16];
#pragma unroll
    for (int o = 0; o < 16; o++) {
        float2 u = upk2(acc[o]);
        res[o] = u.x + u.y + sbias[o];
    }

    if (role == 0) {
        uint4 u;
        __nv_bfloat162 t0 = __floats2bfloat162_rn(res[0], res[1]);
        __nv_bfloat162 t1 = __floats2bfloat162_rn(res[2], res[3]);
        __nv_bfloat162 t2 = __floats2bfloat162_rn(res[4], res[5]);
        __nv_bfloat162 t3 = __floats2bfloat162_rn(res[6], res[7]);
        u.x = *(uint32_t*)&t0; u.y = *(uint32_t*)&t1;
        u.z = *(uint32_t*)&t2; u.w = *(uint32_t*)&t3;
        *(uint4*)(g_qb + (size_t)(b * N_SP + n) * MIDD) = u;
        t0 = __floats2bfloat162_rn(res[8], res[9]);
        t1 = __floats2bfloat162_rn(res[10], res[11]);
        t2 = __floats2bfloat162_rn(res[12], res[13]);
        t3 = __floats2bfloat162_rn(res[14], res[15]);
        u.x = *(uint32_t*)&t0; u.y = *(uint32_t*)&t1;
        u.z = *(uint32_t*)&t2; u.w = *(uint32_t*)&t3;
        *(uint4*)(g_kb + (size_t)(b * N_SP + n) * MIDD) = u;
    } else {
        int c0 = (role - 1) * 16;
#pragma unroll
        for (int j = 0; j < 16; j++)
            g_vb[(size_t)(b * CDIM + c0 + j) * N_SP + n] = __float2bfloat16(res[j]);
    }
}

// ---------------------------------------------------------------------------
// Kernel 2: HMMA flash attention.
//   - scores -> bf16x2 -> ex2.approx.ftz.bf16x2 (half the MUFU ops; exp
//     output IS the PV A-fragment, no separate pack stage in the chain)
//   - denominators via ones-column MMA (row sums on the tensor pipe; no
//     FADD chain, no shuffles; quad lanes hold identical sums)
// Shape: NB=64, MB=64, grid 256, 4 warps, mg=w&1, rows (w>>1)*32.
// ---------------------------------------------------------------------------
__global__ __launch_bounds__(128, 2) void attn_kernel(
    const float* __restrict__ x,
    const float* __restrict__ gamma,
    float* __restrict__ out)
{
    __shared__ __align__(16) char smem[SM_TOTAL];
    uint32_t sb = smem_u32(smem);

    int tid = threadIdx.x;
    int w = tid >> 5;
    int t = tid & 31;
    int mg = w & 1;
    int wrow = (w >> 1) * 32;
    int b = blockIdx.x >> 6;
    int n0 = (blockIdx.x & 63) * NB;

    const __nv_bfloat16* vb0 = g_vb + (size_t)b * CDIM * N_SP;
    const __nv_bfloat16* kb0 = g_kb + (size_t)b * N_SP * MIDD;

    // ---- stage Q tile [64 rows][16B] ----
    if (tid < NB) {
        *(uint4*)(smem + QS_OFF + tid * 16) =
            *(const uint4*)(g_qb + (size_t)(b * N_SP + n0 + tid) * MIDD);
    }

    // ---- prologue: tiles 0,1 -> parity-0 buffers ----
    {
#pragma unroll
        for (int i = 0; i < 8; i++) {
            int ch = tid + 128 * i;
            int tile = ch >> 9;
            int c2 = ch & 511;
            int c = c2 >> 3, q8 = c2 & 7;
            cpasync16(sb + VB_OFF + (tile * 2) * (64 * VSTRB) + c * VSTRB + q8 * 16,
                      vb0 + c * N_SP + tile * MB + q8 * 8);
        }
        {
            int tile = tid >> 6, row = tid & 63;
            cpasync16(sb + KB_OFF + (tile * 2) * 1024 + row * 16,
                      kb0 + (tile * MB + row) * MIDD);
        }
        CP_COMMIT();
    }
    __syncthreads();

    // Q A-frags: rows wrow..wrow+31
    uint32_t qa[4];
    ldsm_x4(qa[0], qa[1], qa[2], qa[3], sb + QS_OFF + (wrow + t) * 16);

    float o0[8][4], o1[8][4];
#pragma unroll
    for (int g2 = 0; g2 < 8; g2++)
#pragma unroll
        for (int j = 0; j < 4; j++) { o0[g2][j] = 0.f; o1[g2][j] = 0.f; }
    float ds0[4] = {0.f, 0.f, 0.f, 0.f};   // ones-MMA denominator accum (rows wrow+, +8)
    float ds1[4] = {0.f, 0.f, 0.f, 0.f};   // rows wrow+16, +24

    int crow_base = ((t & 16) >> 1) + (t & 7);
    int col_base = ((t >> 3) & 1) * 8;

    for (int step = 0; step < NSTEP; step++) {
        // issue next pair of tiles
        if (step + 1 < NSTEP) {
            int par = (step + 1) & 1;
            int m0n = 2 * (step + 1) * MB;
#pragma unroll
            for (int i = 0; i < 8; i++) {
                int ch = tid + 128 * i;
                int tile = ch >> 9;
                int c2 = ch & 511;
                int c = c2 >> 3, q8 = c2 & 7;
                cpasync16(sb + VB_OFF + (tile * 2 + par) * (64 * VSTRB) + c * VSTRB + q8 * 16,
                          vb0 + c * N_SP + m0n + tile * MB + q8 * 8);
            }
            {
                int tile = tid >> 6, row = tid & 63;
                cpasync16(sb + KB_OFF + (tile * 2 + par) * 1024 + row * 16,
                          kb0 + (m0n + tile * MB + row) * MIDD);
            }
            CP_COMMIT();
            asm volatile("cp.async.wait_group 1;" ::: "memory");
        } else {
            asm volatile("cp.async.wait_group 0;" ::: "memory");
        }
        __syncthreads();

        int par = step & 1;
        uint32_t kbase = sb + KB_OFF + (mg * 2 + par) * 1024;
        uint32_t vbase = sb + VB_OFF + (mg * 2 + par) * (64 * VSTRB);

        // ---- all K B-frags for the step ----
        uint32_t kb[8];
        ldsm_x4(kb[0], kb[1], kb[2], kb[3], kbase + t * 16);
        ldsm_x4(kb[4], kb[5], kb[6], kb[7], kbase + (32 + t) * 16);

        // QK stage: scores -> bf16x2 -> ex2.bf16x2; output is the PV A-frag
        auto qk_stage = [&](int ks, uint32_t* P0, uint32_t* P1) {
#pragma unroll
            for (int hf = 0; hf < 2; hf++) {
                float d0[4], d1[4];
                mma_16808(d0, qa[0], qa[1], kb[ks * 2 + hf]);
                mma_16808(d1, qa[2], qa[3], kb[ks * 2 + hf]);
                P0[hf * 2]     = ex2b(pack_bf(d0[0], d0[1]));
                P0[hf * 2 + 1] = ex2b(pack_bf(d0[2], d0[3]));
                P1[hf * 2]     = ex2b(pack_bf(d1[0], d1[1]));
                P1[hf * 2 + 1] = ex2b(pack_bf(d1[2], d1[3]));
            }
        };
        // V fragment loader by flat index (ks*4 + gp)
        auto ldV = [&](uint32_t* v, int flat) {
            int ks = flat >> 2, gp = flat & 3;
            ldsm_x4(v[0], v[1], v[2], v[3],
                    vbase + (gp * 16 + crow_base) * VSTRB + (ks * 16 + col_base) * 2);
        };

        uint32_t pa0[4], pa1[4], pb0[4], pb1[4];
        uint32_t vc[4], vn[4];

        qk_stage(0, pa0, pa1);     // P for ks=0
        ldV(vc, 0);                // V frag (ks=0, gp=0)

#pragma unroll
        for (int ks = 0; ks < 4; ks++) {
            // next K-step's QK+exp BEFORE this K-step's PV (pipe overlap)
            if (ks < 3) qk_stage(ks + 1, pb0, pb1);
            // denominator row-sums on the tensor pipe (B = ones)
            mma_16816(ds0, pa0, ONESB, ONESB);
            mma_16816(ds1, pa1, ONESB, ONESB);
#pragma unroll
            for (int gp = 0; gp < 4; gp++) {
                int nxt = ks * 4 + gp + 1;
                if (nxt < 16) ldV(vn, nxt);     // prefetch next V frag
                mma_16816(o0[gp * 2],     pa0, vc[0], vc[1]);
                mma_16816(o0[gp * 2 + 1], pa0, vc[2], vc[3]);
                mma_16816(o1[gp * 2],     pa1, vc[0], vc[1]);
                mma_16816(o1[gp * 2 + 1], pa1, vc[2], vc[3]);
#pragma unroll
                for (int j = 0; j < 4; j++) vc[j] = vn[j];
            }
            if (ks < 3) {
#pragma unroll
                for (int j = 0; j < 4; j++) { pa0[j] = pb0[j]; pa1[j] = pb1[j]; }
            }
        }
        __syncthreads();
    }

    // ---- denominators: ds*[0]/[2] hold row sums (identical across quad) ----
    float* dsm = (float*)(smem + EP_DSM);
    float* rs  = (float*)(smem + EP_RS);
    float* Os  = (float*)(smem + EP_OS);
    int r0w = wrow + (t >> 2);

    if (mg == 0) {
        if ((t & 3) == 0) {
            dsm[r0w] = ds0[0]; dsm[r0w + 8] = ds0[2];
            dsm[r0w + 16] = ds1[0]; dsm[r0w + 24] = ds1[2];
        }
#pragma unroll
        for (int g2 = 0; g2 < 8; g2++) {
            int c0 = g2 * 8 + 2 * (t & 3);
            int nA = wrow + (t >> 2);
            Os[c0 * OSTR + nA]            = o0[g2][0];
            Os[(c0 + 1) * OSTR + nA]      = o0[g2][1];
            Os[c0 * OSTR + nA + 8]        = o0[g2][2];
            Os[(c0 + 1) * OSTR + nA + 8]  = o0[g2][3];
            Os[c0 * OSTR + nA + 16]       = o1[g2][0];
            Os[(c0 + 1) * OSTR + nA + 16] = o1[g2][1];
            Os[c0 * OSTR + nA + 24]       = o1[g2][2];
            Os[(c0 + 1) * OSTR + nA + 24] = o1[g2][3];
        }
    }
    __syncthreads();
    if (mg == 1) {
        if ((t & 3) == 0) {
            dsm[r0w] += ds0[0]; dsm[r0w + 8] += ds0[2];
            dsm[r0w + 16] += ds1[0]; dsm[r0w + 24] += ds1[2];
        }
#pragma unroll
        for (int g2 = 0; g2 < 8; g2++) {
            int c0 = g2 * 8 + 2 * (t & 3);
            int nA = wrow + (t >> 2);
            Os[c0 * OSTR + nA]            += o0[g2][0];
            Os[(c0 + 1) * OSTR + nA]      += o0[g2][1];
            Os[c0 * OSTR + nA + 8]        += o0[g2][2];
            Os[(c0 + 1) * OSTR + nA + 8]  += o0[g2][3];
            Os[c0 * OSTR + nA + 16]       += o1[g2][0];
            Os[(c0 + 1) * OSTR + nA + 16] += o1[g2][1];
            Os[c0 * OSTR + nA + 24]       += o1[g2][2];
            Os[(c0 + 1) * OSTR + nA + 24] += o1[g2][3];
        }
    }
    __syncthreads();
    if (tid < NB) rs[tid] = gamma[0] / dsm[tid];
    __syncthreads();

    // ---- coalesced write: out[c][n] = Os*rs + x ----
#pragma unroll
    for (int rr = 0; rr < 8; rr++) {
        int f = tid + 128 * rr;          // float4 id: 64 c-rows x 16 per row
        int c = f >> 4, j4 = f & 15;
        float4 o = *(float4*)&Os[c * OSTR + j4 * 4];
        float4 rv = *(float4*)&rs[j4 * 4];
        size_t base = (size_t)(b * CDIM + c) * N_SP + n0 + j4 * 4;
        float4 xv = *(const float4*)&x[base];
        o.x = fmaf(o.x, rv.x, xv.x);
        o.y = fmaf(o.y, rv.y, xv.y);
        o.z = fmaf(o.z, rv.z, xv.z);
        o.w = fmaf(o.w, rv.w, xv.w);
        *(float4*)&out[base] = o;
    }
}

// ---------------------------------------------------------------------------
extern "C" void kernel_launch(void* const* d_in, const int* in_sizes, int n_in,
                              void* d_out, int out_size)
{
    const float* x     = (const float*)d_in[0];
    const float* Wq    = (const float*)d_in[1];
    const float* bq    = (const float*)d_in[2];
    const float* Wk    = (const float*)d_in[3];
    const float* bk    = (const float*)d_in[4];
    const float* Wv    = (const float*)d_in[5];
    const float* bv    = (const float*)d_in[6];
    const float* gamma = (const float*)d_in[7];
    float* out = (float*)d_out;

    qkv_kernel<<<640, 128>>>(x, Wq, bq, Wk, bk, Wv, bv);
    attn_kernel<<<BDIM * (N_SP / NB), 128>>>(x, gamma, out);
}